// round 4
// baseline (speedup 1.0000x reference)
#include <cuda_runtime.h>
#include <math.h>

#define T_TOK   8192
#define HIDDEN  5120
#define NHEADS  40
#define NKV     10
#define HD      128
#define QKV_COLS 7680   // (40 + 10 + 10) * 128
#define SEQ     1024

// Scratch (device globals — no cudaMalloc allowed)
__device__ float g_qkv[(size_t)T_TOK * QKV_COLS];
__device__ float g_attn[(size_t)T_TOK * HIDDEN];

// ---------------------------------------------------------------------------
// Classic 128x128x8 register-blocked SGEMM body (unchanged from prior rounds;
// kept identical as the control arm of the bisect).
// ---------------------------------------------------------------------------
__device__ __forceinline__ void sgemm_body(
    const float* __restrict__ A, const float* __restrict__ B,
    float* __restrict__ C, int M, int N, int K)
{
    __shared__ float As[8][128];
    __shared__ float Bs[8][128];

    const int tid = threadIdx.x;
    const int tr = tid >> 4;
    const int tc = tid & 15;

    const size_t arow = (size_t)blockIdx.y * 128 + (tid >> 1);
    const int    acol = (tid & 1) << 2;
    const int    as_row = tid >> 1;
    const int    brow = tid >> 5;
    const int    bcol_loc = (tid & 31) << 2;
    const size_t bcol = (size_t)blockIdx.x * 128 + bcol_loc;

    const float* Aptr = A + arow * K + acol;
    const float* Bptr = B + (size_t)brow * N + bcol;

    float acc[8][8];
#pragma unroll
    for (int i = 0; i < 8; i++)
#pragma unroll
        for (int j = 0; j < 8; j++) acc[i][j] = 0.f;

    for (int k0 = 0; k0 < K; k0 += 8) {
        float4 av = *(const float4*)(Aptr + k0);
        As[acol + 0][as_row] = av.x;
        As[acol + 1][as_row] = av.y;
        As[acol + 2][as_row] = av.z;
        As[acol + 3][as_row] = av.w;
        float4 bv = *(const float4*)(Bptr + (size_t)k0 * N);
        *(float4*)&Bs[brow][bcol_loc] = bv;
        __syncthreads();

#pragma unroll
        for (int k = 0; k < 8; k++) {
            float a[8], b[8];
            *(float4*)(a)     = *(const float4*)&As[k][tr * 4];
            *(float4*)(a + 4) = *(const float4*)&As[k][64 + tr * 4];
            *(float4*)(b)     = *(const float4*)&Bs[k][tc * 4];
            *(float4*)(b + 4) = *(const float4*)&Bs[k][64 + tc * 4];
#pragma unroll
            for (int i = 0; i < 8; i++)
#pragma unroll
                for (int j = 0; j < 8; j++)
                    acc[i][j] += a[i] * b[j];
        }
        __syncthreads();
    }

#pragma unroll
    for (int qi = 0; qi < 2; qi++) {
#pragma unroll
        for (int i = 0; i < 4; i++) {
            size_t r = (size_t)blockIdx.y * 128 + qi * 64 + tr * 4 + i;
            float* cp = C + r * N + (size_t)blockIdx.x * 128;
            int ai = qi * 4 + i;
            float4 v0 = make_float4(acc[ai][0], acc[ai][1], acc[ai][2], acc[ai][3]);
            float4 v1 = make_float4(acc[ai][4], acc[ai][5], acc[ai][6], acc[ai][7]);
            *(float4*)(cp + tc * 4) = v0;
            *(float4*)(cp + 64 + tc * 4) = v1;
        }
    }
}

__global__ __launch_bounds__(256) void qkv_gemm_kernel(
    const float* __restrict__ x, const float* __restrict__ w_qkv)
{
    sgemm_body(x, w_qkv, g_qkv, T_TOK, QKV_COLS, HIDDEN);
}

__global__ __launch_bounds__(256) void out_gemm_kernel(
    const float* __restrict__ w_o, float* __restrict__ out)
{
    sgemm_body(g_attn, w_o, out, T_TOK, HIDDEN, HIDDEN);
}

// ---------------------------------------------------------------------------
// Naive RoPE: one thread per (t, head<50, j<64). Direct mirror of reference:
// inv_freq = 10000^(-j/64); pair (j, j+64).
// ---------------------------------------------------------------------------
__global__ __launch_bounds__(256) void rope_naive(const int* __restrict__ positions)
{
    long idx = (long)blockIdx.x * 256 + threadIdx.x;
    if (idx >= (long)T_TOK * 50 * 64) return;
    int j  = (int)(idx & 63);
    int hd = (int)((idx >> 6) % 50);
    int t  = (int)(idx / (64 * 50));

    float pos = (float)positions[t];
    float inv_freq = powf(10000.0f, -(float)j / 64.0f);
    float ang = pos * inv_freq;
    float c = cosf(ang);
    float s = sinf(ang);

    size_t base = (size_t)t * QKV_COLS + (size_t)hd * HD + j;
    float x1 = g_qkv[base];
    float x2 = g_qkv[base + 64];
    g_qkv[base]      = x1 * c - x2 * s;
    g_qkv[base + 64] = x2 * c + x1 * s;
}

// ---------------------------------------------------------------------------
// Naive attention: one warp per (token t, q-head n). Two-pass softmax with the
// full score row in shared memory. No tiling, no online rescaling.
// grid: (8192, 5), block: 256 threads = 8 warps (8 heads).
// ---------------------------------------------------------------------------
__global__ __launch_bounds__(256) void attn_naive()
{
    __shared__ float sc[8][SEQ];   // 32 KB

    const int t    = blockIdx.x;                       // 0..8191
    const int warp = threadIdx.x >> 5;
    const int lane = threadIdx.x & 31;
    const int n    = blockIdx.y * 8 + warp;            // q head 0..39
    const int b    = t >> 10;
    const int q    = t & 1023;
    const int kvh  = n >> 2;                           // kv head = n // 4

    const float* bbase = g_qkv + (size_t)b * SEQ * QKV_COLS;

    // q vector: lane holds dims lane*4 .. lane*4+3 (roped already)
    float4 qv = *(const float4*)(bbase + (size_t)q * QKV_COLS + n * HD + lane * 4);

    const float scale = 0.08838834764831845f;          // 1/sqrt(128)

    // Pass 1: scores + max
    const float* krow = bbase + (NHEADS + kvh) * HD + lane * 4;
    float m = -1e30f;
    for (int s = 0; s <= q; s++) {
        float4 kv = *(const float4*)(krow + (size_t)s * QKV_COLS);
        float d = qv.x * kv.x + qv.y * kv.y + qv.z * kv.z + qv.w * kv.w;
#pragma unroll
        for (int off = 16; off >= 1; off >>= 1)
            d += __shfl_xor_sync(0xffffffffu, d, off);
        d *= scale;                                    // all lanes hold full dot
        if (lane == 0) sc[warp][s] = d;
        m = fmaxf(m, d);
    }
    __syncwarp();

    // exp + sum (strided over lanes)
    float lsum = 0.f;
    for (int s = lane; s <= q; s += 32) {
        float e = __expf(sc[warp][s] - m);
        sc[warp][s] = e;
        lsum += e;
    }
#pragma unroll
    for (int off = 16; off >= 1; off >>= 1)
        lsum += __shfl_xor_sync(0xffffffffu, lsum, off);
    __syncwarp();

    // Pass 2: O = sum_s p_s * V[s]
    const float* vrow = bbase + (NHEADS + NKV + kvh) * HD + lane * 4;
    float ox = 0.f, oy = 0.f, oz = 0.f, ow = 0.f;
    for (int s = 0; s <= q; s++) {
        float p = sc[warp][s];                         // smem broadcast
        float4 vv = *(const float4*)(vrow + (size_t)s * QKV_COLS);
        ox += p * vv.x; oy += p * vv.y; oz += p * vv.z; ow += p * vv.w;
    }

    float invl = 1.f / lsum;
    float* op = g_attn + (size_t)t * HIDDEN + n * HD + lane * 4;
    *(float4*)op = make_float4(ox * invl, oy * invl, oz * invl, ow * invl);
}

// ---------------------------------------------------------------------------
// Bind inputs by unique element counts (order-proof).
// ---------------------------------------------------------------------------
extern "C" void kernel_launch(void* const* d_in, const int* in_sizes, int n_in,
                              void* d_out, int out_size)
{
    const float* x         = nullptr;
    const float* w_qkv     = nullptr;
    const float* w_o       = nullptr;
    const int*   positions = nullptr;

    for (int i = 0; i < n_in; i++) {
        switch (in_sizes[i]) {
            case 41943040: x         = (const float*)d_in[i]; break;
            case 39321600: w_qkv     = (const float*)d_in[i]; break;
            case 26214400: w_o       = (const float*)d_in[i]; break;
            case 8192:     positions = (const int*)  d_in[i]; break;
            default: break;
        }
    }
    float* out = (float*)d_out;

    // 1. QKV projection -> g_qkv
    qkv_gemm_kernel<<<dim3(QKV_COLS / 128, T_TOK / 128), 256>>>(x, w_qkv);

    // 2. RoPE in place on q,k heads
    long nrope = (long)T_TOK * 50 * 64;
    rope_naive<<<(int)(nrope / 256), 256>>>(positions);

    // 3. Naive two-pass attention -> g_attn
    attn_naive<<<dim3(T_TOK, 5), 256>>>();

    // 4. Output projection -> d_out
    out_gemm_kernel<<<dim3(HIDDEN / 128, T_TOK / 128), 256>>>(w_o, out);
}

// round 5
// speedup vs baseline: 1.2927x; 1.2927x over previous
#include <cuda_runtime.h>
#include <cuda_bf16.h>
#include <mma.h>
#include <math.h>

using namespace nvcuda;

#define T_TOK   8192
#define HIDDEN  5120
#define NHEADS  40
#define NKV     10
#define HD      128
#define QKV_COLS 7680   // (40 + 10 + 10) * 128
#define SEQ     1024

// Scratch (device globals — no cudaMalloc allowed)
__device__ float g_qkv[(size_t)T_TOK * QKV_COLS];
__device__ float g_attn[(size_t)T_TOK * HIDDEN];

// bf16 hi/lo split operands
__device__ __nv_bfloat16 g_xh[(size_t)T_TOK * HIDDEN];
__device__ __nv_bfloat16 g_xl[(size_t)T_TOK * HIDDEN];
__device__ __nv_bfloat16 g_wqh[(size_t)HIDDEN * QKV_COLS];
__device__ __nv_bfloat16 g_wql[(size_t)HIDDEN * QKV_COLS];
__device__ __nv_bfloat16 g_woh[(size_t)NHEADS * HD * HIDDEN];
__device__ __nv_bfloat16 g_wol[(size_t)NHEADS * HD * HIDDEN];
__device__ __nv_bfloat16 g_oh[(size_t)T_TOK * HIDDEN];
__device__ __nv_bfloat16 g_ol[(size_t)T_TOK * HIDDEN];

// ---------------------------------------------------------------------------
// fp32 -> (bf16 hi, bf16 lo) split, vectorized float4. n4 = elems/4.
// ---------------------------------------------------------------------------
__device__ __forceinline__ void split_body(const float* __restrict__ src,
                                           __nv_bfloat16* __restrict__ hi,
                                           __nv_bfloat16* __restrict__ lo,
                                           long n4)
{
    long i = (long)blockIdx.x * blockDim.x + threadIdx.x;
    if (i >= n4) return;
    float4 a = ((const float4*)src)[i];
    __nv_bfloat16 hx = __float2bfloat16(a.x);
    __nv_bfloat16 hy = __float2bfloat16(a.y);
    __nv_bfloat16 hz = __float2bfloat16(a.z);
    __nv_bfloat16 hw = __float2bfloat16(a.w);
    __nv_bfloat162* hp = (__nv_bfloat162*)hi;
    hp[i * 2 + 0] = __nv_bfloat162(hx, hy);
    hp[i * 2 + 1] = __nv_bfloat162(hz, hw);
    __nv_bfloat16 lx = __float2bfloat16(a.x - __bfloat162float(hx));
    __nv_bfloat16 ly = __float2bfloat16(a.y - __bfloat162float(hy));
    __nv_bfloat16 lz = __float2bfloat16(a.z - __bfloat162float(hz));
    __nv_bfloat16 lw = __float2bfloat16(a.w - __bfloat162float(hw));
    __nv_bfloat162* lp = (__nv_bfloat162*)lo;
    lp[i * 2 + 0] = __nv_bfloat162(lx, ly);
    lp[i * 2 + 1] = __nv_bfloat162(lz, lw);
}

__global__ __launch_bounds__(256) void split_x(const float* __restrict__ x)
{ split_body(x, g_xh, g_xl, (long)T_TOK * HIDDEN / 4); }

__global__ __launch_bounds__(256) void split_wqkv(const float* __restrict__ w)
{ split_body(w, g_wqh, g_wql, (long)HIDDEN * QKV_COLS / 4); }

__global__ __launch_bounds__(256) void split_wo(const float* __restrict__ w)
{ split_body(w, g_woh, g_wol, (long)NHEADS * HD * HIDDEN / 4); }

__global__ __launch_bounds__(256) void split_attn()
{ split_body(g_attn, g_oh, g_ol, (long)T_TOK * HIDDEN / 4); }

// ---------------------------------------------------------------------------
// bf16x3 tensor-core GEMM: C = Ah*Bh + Ah*Bl + Al*Bh  (fp32 accumulate).
// A [M,K] rm, B [K,N] rm, C [M,N] rm. Block 128x128, K-chunk 16.
// 256 threads = 8 warps in 4x2 grid; warp tile 32x64 (2x4 wmma 16x16x16).
// ---------------------------------------------------------------------------
__device__ __forceinline__ void gemm3_body(
    const __nv_bfloat16* __restrict__ Ah, const __nv_bfloat16* __restrict__ Al,
    const __nv_bfloat16* __restrict__ Bh, const __nv_bfloat16* __restrict__ Bl,
    float* __restrict__ C, int M, int N, int K)
{
    // sA padded to 24 (row stride 48B) for conflict-free ldmatrix row gather;
    // sB padded to 136 (row stride 272B) likewise.
    __shared__ __align__(16) __nv_bfloat16 sA[2][128][24];
    __shared__ __align__(16) __nv_bfloat16 sB[2][16][136];

    const int tid = threadIdx.x;
    const int wid = tid >> 5;
    const int warp_m = wid & 3;     // 32-row slab
    const int warp_n = wid >> 2;    // 64-col slab
    const int bm = blockIdx.y * 128;
    const int bn = blockIdx.x * 128;

    wmma::fragment<wmma::accumulator, 16, 16, 16, float> c[2][4];
#pragma unroll
    for (int mt = 0; mt < 2; mt++)
#pragma unroll
        for (int nt = 0; nt < 4; nt++) wmma::fill_fragment(c[mt][nt], 0.0f);

    const int sel = tid >> 7;        // 0: hi matrices, 1: lo matrices
    const int idx = tid & 127;
    const __nv_bfloat16* Asrc = sel ? Al : Ah;
    const __nv_bfloat16* Bsrc = sel ? Bl : Bh;
    const int br = idx >> 3;               // B row 0..15
    const int bc = (idx & 7) * 16;         // B col seg

    const __nv_bfloat16* agp = Asrc + (size_t)(bm + idx) * K;
    const __nv_bfloat16* bgp = Bsrc + (size_t)br * N + bn + bc;

    for (int k0 = 0; k0 < K; k0 += 16) {
        // A: 16 bf16 (32B) per thread -> row idx of sA[sel]
        uint4 a0 = *(const uint4*)(agp + k0);
        uint4 a1 = *(const uint4*)(agp + k0 + 8);
        uint2* ad = (uint2*)&sA[sel][idx][0];
        ad[0] = make_uint2(a0.x, a0.y);
        ad[1] = make_uint2(a0.z, a0.w);
        ad[2] = make_uint2(a1.x, a1.y);
        ad[3] = make_uint2(a1.z, a1.w);
        // B: 16 bf16 per thread -> sB[sel][br][bc..bc+16)
        const __nv_bfloat16* bg = bgp + (size_t)k0 * N;
        uint4 b0 = *(const uint4*)(bg);
        uint4 b1 = *(const uint4*)(bg + 8);
        *(uint4*)&sB[sel][br][bc]     = b0;
        *(uint4*)&sB[sel][br][bc + 8] = b1;
        __syncthreads();

        wmma::fragment<wmma::matrix_a, 16, 16, 16, __nv_bfloat16, wmma::row_major> fah[2], fal[2];
        wmma::fragment<wmma::matrix_b, 16, 16, 16, __nv_bfloat16, wmma::row_major> fbh[4], fbl[4];
#pragma unroll
        for (int mt = 0; mt < 2; mt++) {
            wmma::load_matrix_sync(fah[mt], &sA[0][warp_m * 32 + mt * 16][0], 24);
            wmma::load_matrix_sync(fal[mt], &sA[1][warp_m * 32 + mt * 16][0], 24);
        }
#pragma unroll
        for (int nt = 0; nt < 4; nt++) {
            wmma::load_matrix_sync(fbh[nt], &sB[0][0][warp_n * 64 + nt * 16], 136);
            wmma::load_matrix_sync(fbl[nt], &sB[1][0][warp_n * 64 + nt * 16], 136);
        }
#pragma unroll
        for (int mt = 0; mt < 2; mt++)
#pragma unroll
            for (int nt = 0; nt < 4; nt++) {
                wmma::mma_sync(c[mt][nt], fah[mt], fbh[nt], c[mt][nt]);
                wmma::mma_sync(c[mt][nt], fah[mt], fbl[nt], c[mt][nt]);
                wmma::mma_sync(c[mt][nt], fal[mt], fbh[nt], c[mt][nt]);
            }
        __syncthreads();
    }

#pragma unroll
    for (int mt = 0; mt < 2; mt++)
#pragma unroll
        for (int nt = 0; nt < 4; nt++) {
            float* cp = C + (size_t)(bm + warp_m * 32 + mt * 16) * N
                          + bn + warp_n * 64 + nt * 16;
            wmma::store_matrix_sync(cp, c[mt][nt], N, wmma::mem_row_major);
        }
}

__global__ __launch_bounds__(256) void qkv_gemm_kernel()
{ gemm3_body(g_xh, g_xl, g_wqh, g_wql, g_qkv, T_TOK, QKV_COLS, HIDDEN); }

__global__ __launch_bounds__(256) void out_gemm_kernel(float* __restrict__ out)
{ gemm3_body(g_oh, g_ol, g_woh, g_wol, out, T_TOK, HIDDEN, HIDDEN); }

// ---------------------------------------------------------------------------
// Naive RoPE (unchanged from round 4 — verified correct).
// ---------------------------------------------------------------------------
__global__ __launch_bounds__(256) void rope_naive(const int* __restrict__ positions)
{
    long idx = (long)blockIdx.x * 256 + threadIdx.x;
    if (idx >= (long)T_TOK * 50 * 64) return;
    int j  = (int)(idx & 63);
    int hd = (int)((idx >> 6) % 50);
    int t  = (int)(idx / (64 * 50));

    float pos = (float)positions[t];
    float inv_freq = powf(10000.0f, -(float)j / 64.0f);
    float ang = pos * inv_freq;
    float c = cosf(ang);
    float s = sinf(ang);

    size_t base = (size_t)t * QKV_COLS + (size_t)hd * HD + j;
    float x1 = g_qkv[base];
    float x2 = g_qkv[base + 64];
    g_qkv[base]      = x1 * c - x2 * s;
    g_qkv[base + 64] = x2 * c + x1 * s;
}

// ---------------------------------------------------------------------------
// Naive attention (unchanged from round 4 — verified correct).
// One warp per (token, q-head); two-pass softmax, full row in SMEM.
// ---------------------------------------------------------------------------
__global__ __launch_bounds__(256) void attn_naive()
{
    __shared__ float sc[8][SEQ];   // 32 KB

    const int t    = blockIdx.x;
    const int warp = threadIdx.x >> 5;
    const int lane = threadIdx.x & 31;
    const int n    = blockIdx.y * 8 + warp;
    const int b    = t >> 10;
    const int q    = t & 1023;
    const int kvh  = n >> 2;

    const float* bbase = g_qkv + (size_t)b * SEQ * QKV_COLS;

    float4 qv = *(const float4*)(bbase + (size_t)q * QKV_COLS + n * HD + lane * 4);

    const float scale = 0.08838834764831845f;

    const float* krow = bbase + (NHEADS + kvh) * HD + lane * 4;
    float m = -1e30f;
    for (int s = 0; s <= q; s++) {
        float4 kv = *(const float4*)(krow + (size_t)s * QKV_COLS);
        float d = qv.x * kv.x + qv.y * kv.y + qv.z * kv.z + qv.w * kv.w;
#pragma unroll
        for (int off = 16; off >= 1; off >>= 1)
            d += __shfl_xor_sync(0xffffffffu, d, off);
        d *= scale;
        if (lane == 0) sc[warp][s] = d;
        m = fmaxf(m, d);
    }
    __syncwarp();

    float lsum = 0.f;
    for (int s = lane; s <= q; s += 32) {
        float e = __expf(sc[warp][s] - m);
        sc[warp][s] = e;
        lsum += e;
    }
#pragma unroll
    for (int off = 16; off >= 1; off >>= 1)
        lsum += __shfl_xor_sync(0xffffffffu, lsum, off);
    __syncwarp();

    const float* vrow = bbase + (NHEADS + NKV + kvh) * HD + lane * 4;
    float ox = 0.f, oy = 0.f, oz = 0.f, ow = 0.f;
    for (int s = 0; s <= q; s++) {
        float p = sc[warp][s];
        float4 vv = *(const float4*)(vrow + (size_t)s * QKV_COLS);
        ox += p * vv.x; oy += p * vv.y; oz += p * vv.z; ow += p * vv.w;
    }

    float invl = 1.f / lsum;
    float* op = g_attn + (size_t)t * HIDDEN + n * HD + lane * 4;
    *(float4*)op = make_float4(ox * invl, oy * invl, oz * invl, ow * invl);
}

// ---------------------------------------------------------------------------
extern "C" void kernel_launch(void* const* d_in, const int* in_sizes, int n_in,
                              void* d_out, int out_size)
{
    const float* x         = nullptr;
    const float* w_qkv     = nullptr;
    const float* w_o       = nullptr;
    const int*   positions = nullptr;

    for (int i = 0; i < n_in; i++) {
        switch (in_sizes[i]) {
            case 41943040: x         = (const float*)d_in[i]; break;
            case 39321600: w_qkv     = (const float*)d_in[i]; break;
            case 26214400: w_o       = (const float*)d_in[i]; break;
            case 8192:     positions = (const int*)  d_in[i]; break;
            default: break;
        }
    }
    float* out = (float*)d_out;

    // 0. hi/lo splits
    split_x   <<<(int)((long)T_TOK * HIDDEN / 4 / 256), 256>>>(x);
    split_wqkv<<<(int)((long)HIDDEN * QKV_COLS / 4 / 256), 256>>>(w_qkv);
    split_wo  <<<(int)((long)NHEADS * HD * HIDDEN / 4 / 256), 256>>>(w_o);

    // 1. QKV projection (tensor cores, bf16x3) -> g_qkv
    qkv_gemm_kernel<<<dim3(QKV_COLS / 128, T_TOK / 128), 256>>>();

    // 2. RoPE in place
    long nrope = (long)T_TOK * 50 * 64;
    rope_naive<<<(int)(nrope / 256), 256>>>(positions);

    // 3. Attention -> g_attn
    attn_naive<<<dim3(T_TOK, 5), 256>>>();

    // 4. Split attention output, then O projection (tensor cores) -> d_out
    split_attn<<<(int)((long)T_TOK * HIDDEN / 4 / 256), 256>>>();
    out_gemm_kernel<<<dim3(HIDDEN / 128, T_TOK / 128), 256>>>(out);
}

// round 6
// speedup vs baseline: 1.7659x; 1.3661x over previous
#include <cuda_runtime.h>
#include <cuda_bf16.h>
#include <mma.h>
#include <math.h>

using namespace nvcuda;

#define T_TOK   8192
#define HIDDEN  5120
#define NHEADS  40
#define NKV     10
#define HD      128
#define QKV_COLS 7680   // (40 + 10 + 10) * 128
#define SEQ     1024

// Scratch (device globals — no cudaMalloc allowed)
__device__ float g_qkv[(size_t)T_TOK * QKV_COLS];   // UNroped; rope applied in attn
__device__ float g_attn[(size_t)T_TOK * HIDDEN];

// bf16 hi/lo split operands for the projections
__device__ __nv_bfloat16 g_xh[(size_t)T_TOK * HIDDEN];
__device__ __nv_bfloat16 g_xl[(size_t)T_TOK * HIDDEN];
__device__ __nv_bfloat16 g_wqh[(size_t)HIDDEN * QKV_COLS];
__device__ __nv_bfloat16 g_wql[(size_t)HIDDEN * QKV_COLS];
__device__ __nv_bfloat16 g_woh[(size_t)NHEADS * HD * HIDDEN];
__device__ __nv_bfloat16 g_wol[(size_t)NHEADS * HD * HIDDEN];
__device__ __nv_bfloat16 g_oh[(size_t)T_TOK * HIDDEN];
__device__ __nv_bfloat16 g_ol[(size_t)T_TOK * HIDDEN];

// RoPE tables: [pos 0..1023][j 0..63]
__device__ float g_rcos[SEQ * 64];
__device__ float g_rsin[SEQ * 64];

// ---------------------------------------------------------------------------
__global__ __launch_bounds__(256) void rope_table_kernel()
{
    int idx = blockIdx.x * 256 + threadIdx.x;      // pos*64 + j
    if (idx >= SEQ * 64) return;
    int pos = idx >> 6;
    int j = idx & 63;
    float inv_freq = powf(10000.0f, -(float)j / 64.0f);
    float ang = (float)pos * inv_freq;
    g_rcos[idx] = cosf(ang);
    g_rsin[idx] = sinf(ang);
}

// ---------------------------------------------------------------------------
// fp32 -> (bf16 hi, bf16 lo) split, vectorized float4. n4 = elems/4.
// ---------------------------------------------------------------------------
__device__ __forceinline__ void split_body(const float* __restrict__ src,
                                           __nv_bfloat16* __restrict__ hi,
                                           __nv_bfloat16* __restrict__ lo,
                                           long n4)
{
    long i = (long)blockIdx.x * blockDim.x + threadIdx.x;
    if (i >= n4) return;
    float4 a = ((const float4*)src)[i];
    __nv_bfloat16 hx = __float2bfloat16(a.x);
    __nv_bfloat16 hy = __float2bfloat16(a.y);
    __nv_bfloat16 hz = __float2bfloat16(a.z);
    __nv_bfloat16 hw = __float2bfloat16(a.w);
    __nv_bfloat162* hp = (__nv_bfloat162*)hi;
    hp[i * 2 + 0] = __nv_bfloat162(hx, hy);
    hp[i * 2 + 1] = __nv_bfloat162(hz, hw);
    __nv_bfloat16 lx = __float2bfloat16(a.x - __bfloat162float(hx));
    __nv_bfloat16 ly = __float2bfloat16(a.y - __bfloat162float(hy));
    __nv_bfloat16 lz = __float2bfloat16(a.z - __bfloat162float(hz));
    __nv_bfloat16 lw = __float2bfloat16(a.w - __bfloat162float(hw));
    __nv_bfloat162* lp = (__nv_bfloat162*)lo;
    lp[i * 2 + 0] = __nv_bfloat162(lx, ly);
    lp[i * 2 + 1] = __nv_bfloat162(lz, lw);
}

__global__ __launch_bounds__(256) void split_x(const float* __restrict__ x)
{ split_body(x, g_xh, g_xl, (long)T_TOK * HIDDEN / 4); }

__global__ __launch_bounds__(256) void split_wqkv(const float* __restrict__ w)
{ split_body(w, g_wqh, g_wql, (long)HIDDEN * QKV_COLS / 4); }

__global__ __launch_bounds__(256) void split_wo(const float* __restrict__ w)
{ split_body(w, g_woh, g_wol, (long)NHEADS * HD * HIDDEN / 4); }

__global__ __launch_bounds__(256) void split_attn()
{ split_body(g_attn, g_oh, g_ol, (long)T_TOK * HIDDEN / 4); }

// ---------------------------------------------------------------------------
// bf16x3 tensor-core GEMM (unchanged from round 5 — the control arm).
// ---------------------------------------------------------------------------
__device__ __forceinline__ void gemm3_body(
    const __nv_bfloat16* __restrict__ Ah, const __nv_bfloat16* __restrict__ Al,
    const __nv_bfloat16* __restrict__ Bh, const __nv_bfloat16* __restrict__ Bl,
    float* __restrict__ C, int M, int N, int K)
{
    __shared__ __align__(16) __nv_bfloat16 sA[2][128][24];
    __shared__ __align__(16) __nv_bfloat16 sB[2][16][136];

    const int tid = threadIdx.x;
    const int wid = tid >> 5;
    const int warp_m = wid & 3;
    const int warp_n = wid >> 2;
    const int bm = blockIdx.y * 128;
    const int bn = blockIdx.x * 128;

    wmma::fragment<wmma::accumulator, 16, 16, 16, float> c[2][4];
#pragma unroll
    for (int mt = 0; mt < 2; mt++)
#pragma unroll
        for (int nt = 0; nt < 4; nt++) wmma::fill_fragment(c[mt][nt], 0.0f);

    const int sel = tid >> 7;
    const int idx = tid & 127;
    const __nv_bfloat16* Asrc = sel ? Al : Ah;
    const __nv_bfloat16* Bsrc = sel ? Bl : Bh;
    const int br = idx >> 3;
    const int bc = (idx & 7) * 16;

    const __nv_bfloat16* agp = Asrc + (size_t)(bm + idx) * K;
    const __nv_bfloat16* bgp = Bsrc + (size_t)br * N + bn + bc;

    for (int k0 = 0; k0 < K; k0 += 16) {
        uint4 a0 = *(const uint4*)(agp + k0);
        uint4 a1 = *(const uint4*)(agp + k0 + 8);
        uint2* ad = (uint2*)&sA[sel][idx][0];
        ad[0] = make_uint2(a0.x, a0.y);
        ad[1] = make_uint2(a0.z, a0.w);
        ad[2] = make_uint2(a1.x, a1.y);
        ad[3] = make_uint2(a1.z, a1.w);
        const __nv_bfloat16* bg = bgp + (size_t)k0 * N;
        uint4 b0 = *(const uint4*)(bg);
        uint4 b1 = *(const uint4*)(bg + 8);
        *(uint4*)&sB[sel][br][bc]     = b0;
        *(uint4*)&sB[sel][br][bc + 8] = b1;
        __syncthreads();

        wmma::fragment<wmma::matrix_a, 16, 16, 16, __nv_bfloat16, wmma::row_major> fah[2], fal[2];
        wmma::fragment<wmma::matrix_b, 16, 16, 16, __nv_bfloat16, wmma::row_major> fbh[4], fbl[4];
#pragma unroll
        for (int mt = 0; mt < 2; mt++) {
            wmma::load_matrix_sync(fah[mt], &sA[0][warp_m * 32 + mt * 16][0], 24);
            wmma::load_matrix_sync(fal[mt], &sA[1][warp_m * 32 + mt * 16][0], 24);
        }
#pragma unroll
        for (int nt = 0; nt < 4; nt++) {
            wmma::load_matrix_sync(fbh[nt], &sB[0][0][warp_n * 64 + nt * 16], 136);
            wmma::load_matrix_sync(fbl[nt], &sB[1][0][warp_n * 64 + nt * 16], 136);
        }
#pragma unroll
        for (int mt = 0; mt < 2; mt++)
#pragma unroll
            for (int nt = 0; nt < 4; nt++) {
                wmma::mma_sync(c[mt][nt], fah[mt], fbh[nt], c[mt][nt]);
                wmma::mma_sync(c[mt][nt], fah[mt], fbl[nt], c[mt][nt]);
                wmma::mma_sync(c[mt][nt], fal[mt], fbh[nt], c[mt][nt]);
            }
        __syncthreads();
    }

#pragma unroll
    for (int mt = 0; mt < 2; mt++)
#pragma unroll
        for (int nt = 0; nt < 4; nt++) {
            float* cp = C + (size_t)(bm + warp_m * 32 + mt * 16) * N
                          + bn + warp_n * 64 + nt * 16;
            wmma::store_matrix_sync(cp, c[mt][nt], N, wmma::mem_row_major);
        }
}

__global__ __launch_bounds__(256) void qkv_gemm_kernel()
{ gemm3_body(g_xh, g_xl, g_wqh, g_wql, g_qkv, T_TOK, QKV_COLS, HIDDEN); }

__global__ __launch_bounds__(256) void out_gemm_kernel(float* __restrict__ out)
{ gemm3_body(g_oh, g_ol, g_woh, g_wol, out, T_TOK, HIDDEN, HIDDEN); }

// ---------------------------------------------------------------------------
// wmma flash attention with fused RoPE (hi/lo bf16 everywhere).
// Block: 64-row Q tile of one (b, head); 256 threads = 8 warps.
// grid: (16 qtiles, 40 heads, 8 batches).
// ---------------------------------------------------------------------------
#define ATTN_SMEM (6*64*136*2 + 64*72*4 + 2*64*72*2 + 64*132*4 + 2*64*4)

__global__ __launch_bounds__(256) void attn_wmma(const int* __restrict__ positions)
{
    extern __shared__ char smraw[];
    __nv_bfloat16* sQh = (__nv_bfloat16*)smraw;          // 64 x 136
    __nv_bfloat16* sQl = sQh + 64 * 136;
    __nv_bfloat16* sKh = sQl + 64 * 136;
    __nv_bfloat16* sKl = sKh + 64 * 136;
    __nv_bfloat16* sVh = sKl + 64 * 136;
    __nv_bfloat16* sVl = sVh + 64 * 136;
    float*         sS  = (float*)(sVl + 64 * 136);       // 64 x 72 fp32
    __nv_bfloat16* sPh = (__nv_bfloat16*)(sS + 64 * 72); // 64 x 72
    __nv_bfloat16* sPl = sPh + 64 * 72;
    float*         sO  = (float*)(sPl + 64 * 72);        // 64 x 132 fp32
    float*         sM  = sO + 64 * 132;                  // 64
    float*         sL  = sM + 64;                        // 64

    const int qtile = blockIdx.x;
    const int h     = blockIdx.y;
    const int b     = blockIdx.z;
    const int kvh   = h >> 2;
    const int tid   = threadIdx.x;
    const int wid   = tid >> 5;
    const int warp_m = wid >> 1;        // 0..3 (16 rows)
    const int warp_n = wid & 1;         // 0..1

    const float* base = g_qkv + (size_t)b * SEQ * QKV_COLS;
    const int qcol = h * HD;
    const int kcol = (NHEADS + kvh) * HD;
    const int vcol = (NHEADS + NKV + kvh) * HD;
    const float scale = 0.08838834764831845f;   // 1/sqrt(128)

    // ---- Load Q tile with rope + split ----
    for (int l = tid; l < 64 * 64; l += 256) {
        int r = l >> 6, j = l & 63;
        int grow = qtile * 64 + r;
        int pos = positions[b * SEQ + grow];
        float cs = g_rcos[pos * 64 + j];
        float sn = g_rsin[pos * 64 + j];
        const float* qr = base + (size_t)grow * QKV_COLS + qcol;
        float x1 = qr[j], x2 = qr[j + 64];
        float y1 = x1 * cs - x2 * sn;
        float y2 = x2 * cs + x1 * sn;
        __nv_bfloat16 h1 = __float2bfloat16(y1);
        __nv_bfloat16 h2 = __float2bfloat16(y2);
        sQh[r * 136 + j]      = h1;
        sQh[r * 136 + j + 64] = h2;
        sQl[r * 136 + j]      = __float2bfloat16(y1 - __bfloat162float(h1));
        sQl[r * 136 + j + 64] = __float2bfloat16(y2 - __bfloat162float(h2));
    }
    for (int l = tid; l < 64 * 132; l += 256) sO[l] = 0.f;
    if (tid < 64) { sM[tid] = -1e30f; sL[tid] = 0.f; }
    __syncthreads();

    for (int kt = 0; kt <= qtile; kt++) {
        // ---- Load K (rope+split) and V (split) ----
        for (int l = tid; l < 64 * 64; l += 256) {
            int r = l >> 6, j = l & 63;
            int grow = kt * 64 + r;
            int pos = positions[b * SEQ + grow];
            float cs = g_rcos[pos * 64 + j];
            float sn = g_rsin[pos * 64 + j];
            const float* kr = base + (size_t)grow * QKV_COLS + kcol;
            float x1 = kr[j], x2 = kr[j + 64];
            float y1 = x1 * cs - x2 * sn;
            float y2 = x2 * cs + x1 * sn;
            __nv_bfloat16 h1 = __float2bfloat16(y1);
            __nv_bfloat16 h2 = __float2bfloat16(y2);
            sKh[r * 136 + j]      = h1;
            sKh[r * 136 + j + 64] = h2;
            sKl[r * 136 + j]      = __float2bfloat16(y1 - __bfloat162float(h1));
            sKl[r * 136 + j + 64] = __float2bfloat16(y2 - __bfloat162float(h2));

            const float* vr = base + (size_t)grow * QKV_COLS + vcol;
            float v1 = vr[j], v2 = vr[j + 64];
            __nv_bfloat16 vh1 = __float2bfloat16(v1);
            __nv_bfloat16 vh2 = __float2bfloat16(v2);
            sVh[r * 136 + j]      = vh1;
            sVh[r * 136 + j + 64] = vh2;
            sVl[r * 136 + j]      = __float2bfloat16(v1 - __bfloat162float(vh1));
            sVl[r * 136 + j + 64] = __float2bfloat16(v2 - __bfloat162float(vh2));
        }
        __syncthreads();

        // ---- S = Q K^T (64x64); warp tile 16x32 ----
        {
            wmma::fragment<wmma::accumulator, 16, 16, 16, float> sacc[2];
#pragma unroll
            for (int st = 0; st < 2; st++) wmma::fill_fragment(sacc[st], 0.0f);
#pragma unroll
            for (int kk = 0; kk < 8; kk++) {
                wmma::fragment<wmma::matrix_a, 16, 16, 16, __nv_bfloat16, wmma::row_major> ah, al;
                wmma::load_matrix_sync(ah, &sQh[(warp_m * 16) * 136 + kk * 16], 136);
                wmma::load_matrix_sync(al, &sQl[(warp_m * 16) * 136 + kk * 16], 136);
#pragma unroll
                for (int st = 0; st < 2; st++) {
                    int n0 = warp_n * 32 + st * 16;
                    wmma::fragment<wmma::matrix_b, 16, 16, 16, __nv_bfloat16, wmma::col_major> bh, bl;
                    wmma::load_matrix_sync(bh, &sKh[n0 * 136 + kk * 16], 136);
                    wmma::load_matrix_sync(bl, &sKl[n0 * 136 + kk * 16], 136);
                    wmma::mma_sync(sacc[st], ah, bh, sacc[st]);
                    wmma::mma_sync(sacc[st], ah, bl, sacc[st]);
                    wmma::mma_sync(sacc[st], al, bh, sacc[st]);
                }
            }
#pragma unroll
            for (int st = 0; st < 2; st++)
                wmma::store_matrix_sync(&sS[(warp_m * 16) * 72 + warp_n * 32 + st * 16],
                                        sacc[st], 72, wmma::mem_row_major);
        }
        __syncthreads();

        // ---- online softmax; 4 threads per row ----
        {
            int r = tid >> 2, sub = tid & 3;
            int grow = qtile * 64 + r;
            float vals[16];
            float mx = -1e30f;
#pragma unroll
            for (int i = 0; i < 16; i++) {
                int j = sub * 16 + i;
                float v = sS[r * 72 + j] * scale;
                if (kt * 64 + j > grow) v = -1e30f;
                vals[i] = v;
                mx = fmaxf(mx, v);
            }
            mx = fmaxf(mx, __shfl_xor_sync(0xffffffffu, mx, 1));
            mx = fmaxf(mx, __shfl_xor_sync(0xffffffffu, mx, 2));
            float m_old = sM[r];
            float m_new = fmaxf(m_old, mx);
            float factor = __expf(m_old - m_new);
            float lsum = 0.f;
#pragma unroll
            for (int i = 0; i < 16; i++) {
                float e = __expf(vals[i] - m_new);
                lsum += e;
                __nv_bfloat16 ph = __float2bfloat16(e);
                sPh[r * 72 + sub * 16 + i] = ph;
                sPl[r * 72 + sub * 16 + i] = __float2bfloat16(e - __bfloat162float(ph));
            }
            lsum += __shfl_xor_sync(0xffffffffu, lsum, 1);
            lsum += __shfl_xor_sync(0xffffffffu, lsum, 2);
            if (sub == 0) { sM[r] = m_new; sL[r] = sL[r] * factor + lsum; }
            // rescale O row (stride-4 interleave)
#pragma unroll
            for (int i = 0; i < 32; i++) sO[r * 132 + sub + 4 * i] *= factor;
        }
        __syncthreads();

        // ---- O += P V ; warp tile 16 rows x 64 cols ----
        {
            wmma::fragment<wmma::matrix_a, 16, 16, 16, __nv_bfloat16, wmma::row_major> pa_h[4], pa_l[4];
#pragma unroll
            for (int kk = 0; kk < 4; kk++) {
                wmma::load_matrix_sync(pa_h[kk], &sPh[(warp_m * 16) * 72 + kk * 16], 72);
                wmma::load_matrix_sync(pa_l[kk], &sPl[(warp_m * 16) * 72 + kk * 16], 72);
            }
#pragma unroll
            for (int nt = 0; nt < 4; nt++) {
                int c0 = warp_n * 64 + nt * 16;
                wmma::fragment<wmma::accumulator, 16, 16, 16, float> oacc;
                wmma::load_matrix_sync(oacc, &sO[(warp_m * 16) * 132 + c0], 132, wmma::mem_row_major);
#pragma unroll
                for (int kk = 0; kk < 4; kk++) {
                    wmma::fragment<wmma::matrix_b, 16, 16, 16, __nv_bfloat16, wmma::row_major> vbh, vbl;
                    wmma::load_matrix_sync(vbh, &sVh[(kk * 16) * 136 + c0], 136);
                    wmma::load_matrix_sync(vbl, &sVl[(kk * 16) * 136 + c0], 136);
                    wmma::mma_sync(oacc, pa_h[kk], vbh, oacc);
                    wmma::mma_sync(oacc, pa_h[kk], vbl, oacc);
                    wmma::mma_sync(oacc, pa_l[kk], vbh, oacc);
                }
                wmma::store_matrix_sync(&sO[(warp_m * 16) * 132 + c0], oacc, 132, wmma::mem_row_major);
            }
        }
        __syncthreads();
    }

    // ---- epilogue: normalize, write ----
    {
        int r = tid >> 2, sub = tid & 3;
        float invl = 1.f / sL[r];
        int grow = qtile * 64 + r;
        float* op = g_attn + (size_t)(b * SEQ + grow) * HIDDEN + h * HD;
#pragma unroll
        for (int i = 0; i < 8; i++) {
            int c = sub * 32 + i * 4;
            float4 v = *(float4*)&sO[r * 132 + c];
            v.x *= invl; v.y *= invl; v.z *= invl; v.w *= invl;
            *(float4*)&op[c] = v;
        }
    }
}

// ---------------------------------------------------------------------------
extern "C" void kernel_launch(void* const* d_in, const int* in_sizes, int n_in,
                              void* d_out, int out_size)
{
    const float* x         = nullptr;
    const float* w_qkv     = nullptr;
    const float* w_o       = nullptr;
    const int*   positions = nullptr;

    for (int i = 0; i < n_in; i++) {
        switch (in_sizes[i]) {
            case 41943040: x         = (const float*)d_in[i]; break;
            case 39321600: w_qkv     = (const float*)d_in[i]; break;
            case 26214400: w_o       = (const float*)d_in[i]; break;
            case 8192:     positions = (const int*)  d_in[i]; break;
            default: break;
        }
    }
    float* out = (float*)d_out;

    // 0. rope tables + hi/lo splits
    rope_table_kernel<<<SEQ * 64 / 256, 256>>>();
    split_x   <<<(int)((long)T_TOK * HIDDEN / 4 / 256), 256>>>(x);
    split_wqkv<<<(int)((long)HIDDEN * QKV_COLS / 4 / 256), 256>>>(w_qkv);
    split_wo  <<<(int)((long)NHEADS * HD * HIDDEN / 4 / 256), 256>>>(w_o);

    // 1. QKV projection (tensor cores, bf16x3) -> g_qkv (unroped)
    qkv_gemm_kernel<<<dim3(QKV_COLS / 128, T_TOK / 128), 256>>>();

    // 2. Flash attention (wmma, fused rope) -> g_attn
    cudaFuncSetAttribute(attn_wmma, cudaFuncAttributeMaxDynamicSharedMemorySize, ATTN_SMEM);
    attn_wmma<<<dim3(16, NHEADS, 8), 256, ATTN_SMEM>>>(positions);

    // 3. Split attention output, then O projection (tensor cores) -> d_out
    split_attn<<<(int)((long)T_TOK * HIDDEN / 4 / 256), 256>>>();
    out_gemm_kernel<<<dim3(HIDDEN / 128, T_TOK / 128), 256>>>(out);
}

// round 8
// speedup vs baseline: 2.2760x; 1.2888x over previous
#include <cuda_runtime.h>
#include <cuda_bf16.h>
#include <mma.h>
#include <math.h>

using namespace nvcuda;

#define T_TOK   8192
#define HIDDEN  5120
#define NHEADS  40
#define NKV     10
#define HD      128
#define QKV_COLS 7680   // (40 + 10 + 10) * 128
#define SEQ     1024

// Scratch (device globals — no cudaMalloc allowed)
__device__ float g_qkv[(size_t)T_TOK * QKV_COLS];   // UNroped; rope applied in attn

// bf16 hi/lo split operands for the projections
__device__ __nv_bfloat16 g_xh[(size_t)T_TOK * HIDDEN];
__device__ __nv_bfloat16 g_xl[(size_t)T_TOK * HIDDEN];
__device__ __nv_bfloat16 g_wqh[(size_t)HIDDEN * QKV_COLS];
__device__ __nv_bfloat16 g_wql[(size_t)HIDDEN * QKV_COLS];
__device__ __nv_bfloat16 g_woh[(size_t)NHEADS * HD * HIDDEN];
__device__ __nv_bfloat16 g_wol[(size_t)NHEADS * HD * HIDDEN];
__device__ __nv_bfloat16 g_oh[(size_t)T_TOK * HIDDEN];   // attention out hi/lo
__device__ __nv_bfloat16 g_ol[(size_t)T_TOK * HIDDEN];

// RoPE tables: [pos 0..1023][j 0..63]
__device__ float g_rcos[SEQ * 64];
__device__ float g_rsin[SEQ * 64];

// ---------------------------------------------------------------------------
__global__ __launch_bounds__(256) void rope_table_kernel()
{
    int idx = blockIdx.x * 256 + threadIdx.x;
    if (idx >= SEQ * 64) return;
    int pos = idx >> 6;
    int j = idx & 63;
    float inv_freq = powf(10000.0f, -(float)j / 64.0f);
    float ang = (float)pos * inv_freq;
    g_rcos[idx] = cosf(ang);
    g_rsin[idx] = sinf(ang);
}

// ---------------------------------------------------------------------------
// fp32 -> (bf16 hi, bf16 lo) split
// ---------------------------------------------------------------------------
__device__ __forceinline__ void split_body(const float* __restrict__ src,
                                           __nv_bfloat16* __restrict__ hi,
                                           __nv_bfloat16* __restrict__ lo,
                                           long n4)
{
    long i = (long)blockIdx.x * blockDim.x + threadIdx.x;
    if (i >= n4) return;
    float4 a = ((const float4*)src)[i];
    __nv_bfloat16 hx = __float2bfloat16(a.x);
    __nv_bfloat16 hy = __float2bfloat16(a.y);
    __nv_bfloat16 hz = __float2bfloat16(a.z);
    __nv_bfloat16 hw = __float2bfloat16(a.w);
    __nv_bfloat162* hp = (__nv_bfloat162*)hi;
    hp[i * 2 + 0] = __nv_bfloat162(hx, hy);
    hp[i * 2 + 1] = __nv_bfloat162(hz, hw);
    __nv_bfloat16 lx = __float2bfloat16(a.x - __bfloat162float(hx));
    __nv_bfloat16 ly = __float2bfloat16(a.y - __bfloat162float(hy));
    __nv_bfloat16 lz = __float2bfloat16(a.z - __bfloat162float(hz));
    __nv_bfloat16 lw = __float2bfloat16(a.w - __bfloat162float(hw));
    __nv_bfloat162* lp = (__nv_bfloat162*)lo;
    lp[i * 2 + 0] = __nv_bfloat162(lx, ly);
    lp[i * 2 + 1] = __nv_bfloat162(lz, lw);
}

__global__ __launch_bounds__(256) void split_x(const float* __restrict__ x)
{ split_body(x, g_xh, g_xl, (long)T_TOK * HIDDEN / 4); }

__global__ __launch_bounds__(256) void split_wqkv(const float* __restrict__ w)
{ split_body(w, g_wqh, g_wql, (long)HIDDEN * QKV_COLS / 4); }

__global__ __launch_bounds__(256) void split_wo(const float* __restrict__ w)
{ split_body(w, g_woh, g_wol, (long)NHEADS * HD * HIDDEN / 4); }

// ---------------------------------------------------------------------------
// cp.async helpers
// ---------------------------------------------------------------------------
__device__ __forceinline__ void cp_async16(void* smem_dst, const void* gsrc)
{
    unsigned d = (unsigned)__cvta_generic_to_shared(smem_dst);
    asm volatile("cp.async.cg.shared.global [%0], [%1], 16;\n" :: "r"(d), "l"(gsrc));
}
__device__ __forceinline__ void cp_commit()
{ asm volatile("cp.async.commit_group;\n"); }
template<int NREM> __device__ __forceinline__ void cp_wait()
{ asm volatile("cp.async.wait_group %0;\n" :: "n"(NREM)); }

// ---------------------------------------------------------------------------
// bf16x3 tensor-core GEMM with 3-stage cp.async pipeline.
// C = Ah*Bh + Ah*Bl + Al*Bh (fp32 acc). Block 128x128, K-chunk 16.
// 256 threads = 8 warps (4x2); warp tile 32x64.
// TAIL FIX: last iteration's needed group is the NEWEST committed group, so it
// must use wait_group 0 (wait_group 1 would leave it in flight -> stale SMEM).
// ---------------------------------------------------------------------------
#define GSTAGES 3
#define GEMM_SMEM ((GSTAGES*2*128*24 + GSTAGES*2*16*136) * 2)

__device__ __forceinline__ void gemm3_body(
    const __nv_bfloat16* __restrict__ Ah, const __nv_bfloat16* __restrict__ Al,
    const __nv_bfloat16* __restrict__ Bh, const __nv_bfloat16* __restrict__ Bl,
    float* __restrict__ C, int M, int N, int K)
{
    extern __shared__ __align__(16) char smraw[];
    __nv_bfloat16* sAb = (__nv_bfloat16*)smraw;                  // [s][sel][128][24]
    __nv_bfloat16* sBb = sAb + GSTAGES * 2 * 128 * 24;           // [s][sel][16][136]

    const int tid = threadIdx.x;
    const int wid = tid >> 5;
    const int warp_m = wid & 3;
    const int warp_n = wid >> 2;
    const int bm = blockIdx.y * 128;
    const int bn = blockIdx.x * 128;

    const int arow = tid >> 1;
    const int akseg = (tid & 1) * 8;
    const int brow = tid >> 4;
    const int bcseg = (tid & 15) * 8;

    const __nv_bfloat16* agh = Ah + (size_t)(bm + arow) * K + akseg;
    const __nv_bfloat16* agl = Al + (size_t)(bm + arow) * K + akseg;
    const __nv_bfloat16* bgh = Bh + (size_t)brow * N + bn + bcseg;
    const __nv_bfloat16* bgl = Bl + (size_t)brow * N + bn + bcseg;

    #define SA(s, sel, row) (sAb + (((s) * 2 + (sel)) * 128 + (row)) * 24)
    #define SB(s, sel, row) (sBb + (((s) * 2 + (sel)) * 16 + (row)) * 136)

    auto issue = [&](int s, int k0) {
        cp_async16(SA(s, 0, arow) + akseg, agh + k0);
        cp_async16(SA(s, 1, arow) + akseg, agl + k0);
        cp_async16(SB(s, 0, brow) + bcseg, bgh + (size_t)k0 * N);
        cp_async16(SB(s, 1, brow) + bcseg, bgl + (size_t)k0 * N);
        cp_commit();
    };

    wmma::fragment<wmma::accumulator, 16, 16, 16, float> c[2][4];
#pragma unroll
    for (int mt = 0; mt < 2; mt++)
#pragma unroll
        for (int nt = 0; nt < 4; nt++) wmma::fill_fragment(c[mt][nt], 0.0f);

    const int nchunks = K / 16;
    issue(0, 0);
    issue(1, 16);

    for (int ks = 0; ks < nchunks; ks++) {
        // TAIL FIX: on the last chunk the needed group is the newest -> drain all.
        if (ks == nchunks - 1) cp_wait<0>(); else cp_wait<GSTAGES - 2>();
        __syncthreads();
        const int s = ks % GSTAGES;

        wmma::fragment<wmma::matrix_a, 16, 16, 16, __nv_bfloat16, wmma::row_major> fah[2], fal[2];
        wmma::fragment<wmma::matrix_b, 16, 16, 16, __nv_bfloat16, wmma::row_major> fbh[4], fbl[4];
#pragma unroll
        for (int mt = 0; mt < 2; mt++) {
            wmma::load_matrix_sync(fah[mt], SA(s, 0, warp_m * 32 + mt * 16), 24);
            wmma::load_matrix_sync(fal[mt], SA(s, 1, warp_m * 32 + mt * 16), 24);
        }
#pragma unroll
        for (int nt = 0; nt < 4; nt++) {
            wmma::load_matrix_sync(fbh[nt], SB(s, 0, 0) + warp_n * 64 + nt * 16, 136);
            wmma::load_matrix_sync(fbl[nt], SB(s, 1, 0) + warp_n * 64 + nt * 16, 136);
        }
#pragma unroll
        for (int mt = 0; mt < 2; mt++)
#pragma unroll
            for (int nt = 0; nt < 4; nt++) {
                wmma::mma_sync(c[mt][nt], fah[mt], fbh[nt], c[mt][nt]);
                wmma::mma_sync(c[mt][nt], fah[mt], fbl[nt], c[mt][nt]);
                wmma::mma_sync(c[mt][nt], fal[mt], fbh[nt], c[mt][nt]);
            }

        const int kn = ks + GSTAGES - 1;
        if (kn < nchunks) issue(kn % GSTAGES, kn * 16);
    }

#pragma unroll
    for (int mt = 0; mt < 2; mt++)
#pragma unroll
        for (int nt = 0; nt < 4; nt++) {
            float* cp = C + (size_t)(bm + warp_m * 32 + mt * 16) * N
                          + bn + warp_n * 64 + nt * 16;
            wmma::store_matrix_sync(cp, c[mt][nt], N, wmma::mem_row_major);
        }
    #undef SA
    #undef SB
}

__global__ __launch_bounds__(256) void qkv_gemm_kernel()
{ gemm3_body(g_xh, g_xl, g_wqh, g_wql, g_qkv, T_TOK, QKV_COLS, HIDDEN); }

__global__ __launch_bounds__(256) void out_gemm_kernel(float* __restrict__ out)
{ gemm3_body(g_oh, g_ol, g_woh, g_wol, out, T_TOK, HIDDEN, HIDDEN); }

// ---------------------------------------------------------------------------
// wmma flash attention with fused RoPE (hi/lo bf16 everywhere).
// Epilogue writes split bf16 (g_oh/g_ol) directly for the O projection.
// ---------------------------------------------------------------------------
#define ATTN_SMEM (6*64*136*2 + 64*72*4 + 2*64*72*2 + 64*132*4 + 2*64*4)

__global__ __launch_bounds__(256) void attn_wmma(const int* __restrict__ positions)
{
    extern __shared__ char smraw[];
    __nv_bfloat16* sQh = (__nv_bfloat16*)smraw;          // 64 x 136
    __nv_bfloat16* sQl = sQh + 64 * 136;
    __nv_bfloat16* sKh = sQl + 64 * 136;
    __nv_bfloat16* sKl = sKh + 64 * 136;
    __nv_bfloat16* sVh = sKl + 64 * 136;
    __nv_bfloat16* sVl = sVh + 64 * 136;
    float*         sS  = (float*)(sVl + 64 * 136);       // 64 x 72 fp32
    __nv_bfloat16* sPh = (__nv_bfloat16*)(sS + 64 * 72); // 64 x 72
    __nv_bfloat16* sPl = sPh + 64 * 72;
    float*         sO  = (float*)(sPl + 64 * 72);        // 64 x 132 fp32
    float*         sM  = sO + 64 * 132;                  // 64
    float*         sL  = sM + 64;                        // 64

    const int qtile = blockIdx.x;
    const int h     = blockIdx.y;
    const int b     = blockIdx.z;
    const int kvh   = h >> 2;
    const int tid   = threadIdx.x;
    const int wid   = tid >> 5;
    const int warp_m = wid >> 1;
    const int warp_n = wid & 1;

    const float* base = g_qkv + (size_t)b * SEQ * QKV_COLS;
    const int qcol = h * HD;
    const int kcol = (NHEADS + kvh) * HD;
    const int vcol = (NHEADS + NKV + kvh) * HD;
    const float scale = 0.08838834764831845f;

    for (int l = tid; l < 64 * 64; l += 256) {
        int r = l >> 6, j = l & 63;
        int grow = qtile * 64 + r;
        int pos = positions[b * SEQ + grow];
        float cs = g_rcos[pos * 64 + j];
        float sn = g_rsin[pos * 64 + j];
        const float* qr = base + (size_t)grow * QKV_COLS + qcol;
        float x1 = qr[j], x2 = qr[j + 64];
        float y1 = x1 * cs - x2 * sn;
        float y2 = x2 * cs + x1 * sn;
        __nv_bfloat16 h1 = __float2bfloat16(y1);
        __nv_bfloat16 h2 = __float2bfloat16(y2);
        sQh[r * 136 + j]      = h1;
        sQh[r * 136 + j + 64] = h2;
        sQl[r * 136 + j]      = __float2bfloat16(y1 - __bfloat162float(h1));
        sQl[r * 136 + j + 64] = __float2bfloat16(y2 - __bfloat162float(h2));
    }
    for (int l = tid; l < 64 * 132; l += 256) sO[l] = 0.f;
    if (tid < 64) { sM[tid] = -1e30f; sL[tid] = 0.f; }
    __syncthreads();

    for (int kt = 0; kt <= qtile; kt++) {
        for (int l = tid; l < 64 * 64; l += 256) {
            int r = l >> 6, j = l & 63;
            int grow = kt * 64 + r;
            int pos = positions[b * SEQ + grow];
            float cs = g_rcos[pos * 64 + j];
            float sn = g_rsin[pos * 64 + j];
            const float* kr = base + (size_t)grow * QKV_COLS + kcol;
            float x1 = kr[j], x2 = kr[j + 64];
            float y1 = x1 * cs - x2 * sn;
            float y2 = x2 * cs + x1 * sn;
            __nv_bfloat16 h1 = __float2bfloat16(y1);
            __nv_bfloat16 h2 = __float2bfloat16(y2);
            sKh[r * 136 + j]      = h1;
            sKh[r * 136 + j + 64] = h2;
            sKl[r * 136 + j]      = __float2bfloat16(y1 - __bfloat162float(h1));
            sKl[r * 136 + j + 64] = __float2bfloat16(y2 - __bfloat162float(h2));

            const float* vr = base + (size_t)grow * QKV_COLS + vcol;
            float v1 = vr[j], v2 = vr[j + 64];
            __nv_bfloat16 vh1 = __float2bfloat16(v1);
            __nv_bfloat16 vh2 = __float2bfloat16(v2);
            sVh[r * 136 + j]      = vh1;
            sVh[r * 136 + j + 64] = vh2;
            sVl[r * 136 + j]      = __float2bfloat16(v1 - __bfloat162float(vh1));
            sVl[r * 136 + j + 64] = __float2bfloat16(v2 - __bfloat162float(vh2));
        }
        __syncthreads();

        {
            wmma::fragment<wmma::accumulator, 16, 16, 16, float> sacc[2];
#pragma unroll
            for (int st = 0; st < 2; st++) wmma::fill_fragment(sacc[st], 0.0f);
#pragma unroll
            for (int kk = 0; kk < 8; kk++) {
                wmma::fragment<wmma::matrix_a, 16, 16, 16, __nv_bfloat16, wmma::row_major> ah, al;
                wmma::load_matrix_sync(ah, &sQh[(warp_m * 16) * 136 + kk * 16], 136);
                wmma::load_matrix_sync(al, &sQl[(warp_m * 16) * 136 + kk * 16], 136);
#pragma unroll
                for (int st = 0; st < 2; st++) {
                    int n0 = warp_n * 32 + st * 16;
                    wmma::fragment<wmma::matrix_b, 16, 16, 16, __nv_bfloat16, wmma::col_major> bh, bl;
                    wmma::load_matrix_sync(bh, &sKh[n0 * 136 + kk * 16], 136);
                    wmma::load_matrix_sync(bl, &sKl[n0 * 136 + kk * 16], 136);
                    wmma::mma_sync(sacc[st], ah, bh, sacc[st]);
                    wmma::mma_sync(sacc[st], ah, bl, sacc[st]);
                    wmma::mma_sync(sacc[st], al, bh, sacc[st]);
                }
            }
#pragma unroll
            for (int st = 0; st < 2; st++)
                wmma::store_matrix_sync(&sS[(warp_m * 16) * 72 + warp_n * 32 + st * 16],
                                        sacc[st], 72, wmma::mem_row_major);
        }
        __syncthreads();

        {
            int r = tid >> 2, sub = tid & 3;
            int grow = qtile * 64 + r;
            float vals[16];
            float mx = -1e30f;
#pragma unroll
            for (int i = 0; i < 16; i++) {
                int j = sub * 16 + i;
                float v = sS[r * 72 + j] * scale;
                if (kt * 64 + j > grow) v = -1e30f;
                vals[i] = v;
                mx = fmaxf(mx, v);
            }
            mx = fmaxf(mx, __shfl_xor_sync(0xffffffffu, mx, 1));
            mx = fmaxf(mx, __shfl_xor_sync(0xffffffffu, mx, 2));
            float m_old = sM[r];
            float m_new = fmaxf(m_old, mx);
            float factor = __expf(m_old - m_new);
            float lsum = 0.f;
#pragma unroll
            for (int i = 0; i < 16; i++) {
                float e = __expf(vals[i] - m_new);
                lsum += e;
                __nv_bfloat16 ph = __float2bfloat16(e);
                sPh[r * 72 + sub * 16 + i] = ph;
                sPl[r * 72 + sub * 16 + i] = __float2bfloat16(e - __bfloat162float(ph));
            }
            lsum += __shfl_xor_sync(0xffffffffu, lsum, 1);
            lsum += __shfl_xor_sync(0xffffffffu, lsum, 2);
            if (sub == 0) { sM[r] = m_new; sL[r] = sL[r] * factor + lsum; }
#pragma unroll
            for (int i = 0; i < 32; i++) sO[r * 132 + sub + 4 * i] *= factor;
        }
        __syncthreads();

        {
            wmma::fragment<wmma::matrix_a, 16, 16, 16, __nv_bfloat16, wmma::row_major> pa_h[4], pa_l[4];
#pragma unroll
            for (int kk = 0; kk < 4; kk++) {
                wmma::load_matrix_sync(pa_h[kk], &sPh[(warp_m * 16) * 72 + kk * 16], 72);
                wmma::load_matrix_sync(pa_l[kk], &sPl[(warp_m * 16) * 72 + kk * 16], 72);
            }
#pragma unroll
            for (int nt = 0; nt < 4; nt++) {
                int c0 = warp_n * 64 + nt * 16;
                wmma::fragment<wmma::accumulator, 16, 16, 16, float> oacc;
                wmma::load_matrix_sync(oacc, &sO[(warp_m * 16) * 132 + c0], 132, wmma::mem_row_major);
#pragma unroll
                for (int kk = 0; kk < 4; kk++) {
                    wmma::fragment<wmma::matrix_b, 16, 16, 16, __nv_bfloat16, wmma::row_major> vbh, vbl;
                    wmma::load_matrix_sync(vbh, &sVh[(kk * 16) * 136 + c0], 136);
                    wmma::load_matrix_sync(vbl, &sVl[(kk * 16) * 136 + c0], 136);
                    wmma::mma_sync(oacc, pa_h[kk], vbh, oacc);
                    wmma::mma_sync(oacc, pa_h[kk], vbl, oacc);
                    wmma::mma_sync(oacc, pa_l[kk], vbh, oacc);
                }
                wmma::store_matrix_sync(&sO[(warp_m * 16) * 132 + c0], oacc, 132, wmma::mem_row_major);
            }
        }
        __syncthreads();
    }

    // epilogue: normalize + write split bf16 directly (fused split_attn)
    {
        int r = tid >> 2, sub = tid & 3;
        float invl = 1.f / sL[r];
        int grow = qtile * 64 + r;
        size_t rowoff = (size_t)(b * SEQ + grow) * HIDDEN + h * HD;
#pragma unroll
        for (int i = 0; i < 8; i++) {
            int c = sub * 32 + i * 4;
            float4 v = *(float4*)&sO[r * 132 + c];
            v.x *= invl; v.y *= invl; v.z *= invl; v.w *= invl;
            __nv_bfloat16 hx = __float2bfloat16(v.x);
            __nv_bfloat16 hy = __float2bfloat16(v.y);
            __nv_bfloat16 hz = __float2bfloat16(v.z);
            __nv_bfloat16 hw = __float2bfloat16(v.w);
            *(__nv_bfloat162*)&g_oh[rowoff + c]     = __nv_bfloat162(hx, hy);
            *(__nv_bfloat162*)&g_oh[rowoff + c + 2] = __nv_bfloat162(hz, hw);
            __nv_bfloat16 lx = __float2bfloat16(v.x - __bfloat162float(hx));
            __nv_bfloat16 ly = __float2bfloat16(v.y - __bfloat162float(hy));
            __nv_bfloat16 lz = __float2bfloat16(v.z - __bfloat162float(hz));
            __nv_bfloat16 lw = __float2bfloat16(v.w - __bfloat162float(hw));
            *(__nv_bfloat162*)&g_ol[rowoff + c]     = __nv_bfloat162(lx, ly);
            *(__nv_bfloat162*)&g_ol[rowoff + c + 2] = __nv_bfloat162(lz, lw);
        }
    }
}

// ---------------------------------------------------------------------------
extern "C" void kernel_launch(void* const* d_in, const int* in_sizes, int n_in,
                              void* d_out, int out_size)
{
    const float* x         = nullptr;
    const float* w_qkv     = nullptr;
    const float* w_o       = nullptr;
    const int*   positions = nullptr;

    for (int i = 0; i < n_in; i++) {
        switch (in_sizes[i]) {
            case 41943040: x         = (const float*)d_in[i]; break;
            case 39321600: w_qkv     = (const float*)d_in[i]; break;
            case 26214400: w_o       = (const float*)d_in[i]; break;
            case 8192:     positions = (const int*)  d_in[i]; break;
            default: break;
        }
    }
    float* out = (float*)d_out;

    // 0. rope tables + hi/lo splits
    rope_table_kernel<<<SEQ * 64 / 256, 256>>>();
    split_x   <<<(int)((long)T_TOK * HIDDEN / 4 / 256), 256>>>(x);
    split_wqkv<<<(int)((long)HIDDEN * QKV_COLS / 4 / 256), 256>>>(w_qkv);
    split_wo  <<<(int)((long)NHEADS * HD * HIDDEN / 4 / 256), 256>>>(w_o);

    // 1. QKV projection (pipelined bf16x3 tensor cores) -> g_qkv
    cudaFuncSetAttribute(qkv_gemm_kernel, cudaFuncAttributeMaxDynamicSharedMemorySize, GEMM_SMEM);
    qkv_gemm_kernel<<<dim3(QKV_COLS / 128, T_TOK / 128), 256, GEMM_SMEM>>>();

    // 2. Flash attention (wmma, fused rope, fused output split) -> g_oh/g_ol
    cudaFuncSetAttribute(attn_wmma, cudaFuncAttributeMaxDynamicSharedMemorySize, ATTN_SMEM);
    attn_wmma<<<dim3(16, NHEADS, 8), 256, ATTN_SMEM>>>(positions);

    // 3. O projection (pipelined bf16x3 tensor cores) -> d_out
    cudaFuncSetAttribute(out_gemm_kernel, cudaFuncAttributeMaxDynamicSharedMemorySize, GEMM_SMEM);
    out_gemm_kernel<<<dim3(HIDDEN / 128, T_TOK / 128), 256, GEMM_SMEM>>>(out);
}